// round 1
// baseline (speedup 1.0000x reference)
#include <cuda_runtime.h>
#include <cstdint>

// Problem constants (shapes are fixed for this problem instance)
#define N_NODES 50000
#define N_EDGES 600000
#define CH      128          // IN_CH == OUT_CH == 128, HEADS == 1

// ---------------------------------------------------------------------------
// Scratch (no cudaMalloc allowed): aggregation buffer + in-degree counts
// ---------------------------------------------------------------------------
__device__ float d_s[(size_t)N_NODES * CH];   // sum of neighbor features (+ self)
__device__ int   d_cnt[N_NODES];              // in-degree + 1 (self loop)
__device__ int   d_is64;                      // edge_index dtype flag

// ---------------------------------------------------------------------------
// Detect whether edge_index buffer is int64 or int32.
// int64 values are all < 50000 -> high 32 bits zero for every entry.
// int32 buffer read as u64 packs two random indices -> nonzero high word w.h.p.
// ---------------------------------------------------------------------------
__global__ void detect_kernel(const void* __restrict__ ei) {
    const unsigned long long* p = (const unsigned long long*)ei;
    int is64 = 1;
    #pragma unroll
    for (int i = 0; i < 16; i++) {
        if (p[i] >> 32) is64 = 0;
    }
    d_is64 = is64;
}

// ---------------------------------------------------------------------------
// Init: s = x (self-loop contribution), cnt = 1 (self loop)
// ---------------------------------------------------------------------------
__global__ void init_kernel(const float* __restrict__ x, int n_nodes) {
    int i = blockIdx.x * blockDim.x + threadIdx.x;
    int n4 = n_nodes * (CH / 4);
    if (i < n4) {
        ((float4*)d_s)[i] = ((const float4*)x)[i];
    }
    if (i < n_nodes) {
        d_cnt[i] = 1;
    }
}

// ---------------------------------------------------------------------------
// Scatter: one warp per edge. Each lane moves one float4 of the source row
// into the destination row via vectorized global reduction.
// ---------------------------------------------------------------------------
__global__ void scatter_kernel(const float* __restrict__ x,
                               const void* __restrict__ ei,
                               int n_edges) {
    int gwarp = (blockIdx.x * blockDim.x + threadIdx.x) >> 5;
    int lane  = threadIdx.x & 31;
    if (gwarp >= n_edges) return;

    int src = 0, dst = 0;
    if (lane == 0) {
        if (d_is64) {
            const long long* p = (const long long*)ei;
            src = (int)p[gwarp];
            dst = (int)p[n_edges + gwarp];
        } else {
            const int* p = (const int*)ei;
            src = p[gwarp];
            dst = p[n_edges + gwarp];
        }
    }
    src = __shfl_sync(0xFFFFFFFFu, src, 0);
    dst = __shfl_sync(0xFFFFFFFFu, dst, 0);

    float4 v = *(const float4*)(x + (size_t)src * CH + lane * 4);
    float* sp = d_s + (size_t)dst * CH + lane * 4;
    asm volatile("red.global.add.v4.f32 [%0], {%1, %2, %3, %4};"
                 :: "l"(sp), "f"(v.x), "f"(v.y), "f"(v.z), "f"(v.w)
                 : "memory");

    if (lane == 0) atomicAdd(&d_cnt[dst], 1);
}

// ---------------------------------------------------------------------------
// GEMM + epilogue: out = relu( (s @ W) / cnt + bias )
// Tile: BM=64 rows x BN=128 cols (full width), BK=32, 256 threads,
// per-thread microtile TM=8 x TN=4.
// ---------------------------------------------------------------------------
#define GBM 64
#define GBN 128
#define GBK 32

__global__ __launch_bounds__(256)
void gemm_kernel(const float* __restrict__ W,
                 const float* __restrict__ bias,
                 float* __restrict__ out,
                 int n_nodes) {
    __shared__ float As[GBK][GBM + 1];   // +1 pad: conflict-free transposed store
    __shared__ float Bs[GBK][GBN];

    int tid = threadIdx.x;
    int tx  = tid & 31;    // column group: cols [tx*4, tx*4+4)
    int ty  = tid >> 5;    // row group:    rows [ty*8, ty*8+8)
    int row0 = blockIdx.x * GBM;

    float acc[8][4];
    #pragma unroll
    for (int i = 0; i < 8; i++)
        #pragma unroll
        for (int j = 0; j < 4; j++) acc[i][j] = 0.0f;

    for (int k0 = 0; k0 < CH; k0 += GBK) {
        // Load A tile (transposed): As[k][m] = s[(row0+m)*CH + k0+k]
        #pragma unroll
        for (int i = 0; i < 8; i++) {
            int idx = tid + i * 256;          // 0..2047
            int k = idx & 31;
            int m = idx >> 5;
            int row = row0 + m;
            As[k][m] = (row < n_nodes) ? d_s[(size_t)row * CH + k0 + k] : 0.0f;
        }
        // Load B tile: Bs[k][n] = W[(k0+k)*CH + n], float4 vectorized
        #pragma unroll
        for (int i = 0; i < 4; i++) {
            int idx4 = tid + i * 256;         // 0..1023
            int k  = idx4 >> 5;
            int n4 = idx4 & 31;
            *(float4*)&Bs[k][n4 * 4] =
                *(const float4*)(W + (size_t)(k0 + k) * CH + n4 * 4);
        }
        __syncthreads();

        #pragma unroll
        for (int kk = 0; kk < GBK; kk++) {
            float a[8];
            #pragma unroll
            for (int i = 0; i < 8; i++) a[i] = As[kk][ty * 8 + i];
            float4 b4 = *(const float4*)&Bs[kk][tx * 4];
            float b[4] = {b4.x, b4.y, b4.z, b4.w};
            #pragma unroll
            for (int i = 0; i < 8; i++)
                #pragma unroll
                for (int j = 0; j < 4; j++)
                    acc[i][j] = fmaf(a[i], b[j], acc[i][j]);
        }
        __syncthreads();
    }

    // Epilogue: divide by count, add bias, relu
    float4 bb4 = *(const float4*)(bias + tx * 4);
    float bb[4] = {bb4.x, bb4.y, bb4.z, bb4.w};
    #pragma unroll
    for (int i = 0; i < 8; i++) {
        int row = row0 + ty * 8 + i;
        if (row < n_nodes) {
            float inv = 1.0f / (float)d_cnt[row];
            float4 o;
            o.x = fmaxf(acc[i][0] * inv + bb[0], 0.0f);
            o.y = fmaxf(acc[i][1] * inv + bb[1], 0.0f);
            o.z = fmaxf(acc[i][2] * inv + bb[2], 0.0f);
            o.w = fmaxf(acc[i][3] * inv + bb[3], 0.0f);
            *(float4*)(out + (size_t)row * CH + tx * 4) = o;
        }
    }
}

// ---------------------------------------------------------------------------
// kernel_launch
// Inputs (metadata order): x[f32 N*128], edge_index[int 2*E], weight[f32 128*128],
//                          u[f32 128*1], c[f32 1], bias[f32 128]
// u and c are mathematically dead (HEADS==1 => softmax over 1 element == 1).
// ---------------------------------------------------------------------------
extern "C" void kernel_launch(void* const* d_in, const int* in_sizes, int n_in,
                              void* d_out, int out_size) {
    const float* x    = (const float*)d_in[0];
    const void*  ei   = d_in[1];
    const float* W    = (const float*)d_in[2];
    const float* bias = (const float*)d_in[5];
    float* out = (float*)d_out;

    int n_nodes = in_sizes[0] / CH;
    int n_edges = in_sizes[1] / 2;

    // 1) dtype sniff for edge_index
    detect_kernel<<<1, 1>>>(ei);

    // 2) s = x, cnt = 1
    int init_threads = n_nodes * (CH / 4);         // 1.6M float4 copies
    init_kernel<<<(init_threads + 255) / 256, 256>>>(x, n_nodes);

    // 3) scatter: warp per edge
    int warps_per_block = 256 / 32;
    int blocks = (n_edges + warps_per_block - 1) / warps_per_block;
    scatter_kernel<<<blocks, 256>>>(x, ei, n_edges);

    // 4) GEMM + epilogue
    int gblocks = (n_nodes + GBM - 1) / GBM;
    gemm_kernel<<<gblocks, 256>>>(W, bias, out, n_nodes);
}

// round 2
// speedup vs baseline: 1.3796x; 1.3796x over previous
#include <cuda_runtime.h>
#include <cstdint>

// Problem constants (fixed shapes for this instance)
#define N_NODES 50000
#define N_EDGES 600000
#define CH      128          // IN_CH == OUT_CH == 128, HEADS == 1
#define CAP     96           // per-node bucket capacity (Poisson(12) max ~ 30)

// ---------------------------------------------------------------------------
// Scratch (no cudaMalloc allowed)
// ---------------------------------------------------------------------------
__device__ float d_s[(size_t)N_NODES * CH];        // aggregated features
__device__ int   d_deg[N_NODES];                   // in-degree (excl. self loop)
__device__ int   d_bucket[(size_t)N_NODES * CAP];  // per-dst source lists
__device__ int   d_is64;                           // edge_index dtype flag

// ---------------------------------------------------------------------------
// Detect whether edge_index buffer is int64 or int32.
// ---------------------------------------------------------------------------
__global__ void detect_kernel(const void* __restrict__ ei) {
    const unsigned long long* p = (const unsigned long long*)ei;
    int is64 = 1;
    #pragma unroll
    for (int i = 0; i < 16; i++) {
        if (p[i] >> 32) is64 = 0;
    }
    d_is64 = is64;
}

// ---------------------------------------------------------------------------
// Zero: d_s = 0, deg = 0   (d_s must be clean each call: graph replays)
// ---------------------------------------------------------------------------
__global__ void zero_kernel(int n_nodes) {
    int i = blockIdx.x * blockDim.x + threadIdx.x;
    int n4 = n_nodes * (CH / 4);
    if (i < n4) ((float4*)d_s)[i] = make_float4(0.f, 0.f, 0.f, 0.f);
    if (i < n_nodes) d_deg[i] = 0;
}

// ---------------------------------------------------------------------------
// Histogram + bucket fill: thread per edge.
// pos = atomicAdd(deg[dst]); bucket[dst][pos] = src.
// Overflow (pos >= CAP, never expected for this input): red-add x[src] row
// directly into d_s so correctness holds for any input.
// ---------------------------------------------------------------------------
__global__ void histo_fill_kernel(const float* __restrict__ x,
                                  const void* __restrict__ ei,
                                  int n_edges) {
    int e = blockIdx.x * blockDim.x + threadIdx.x;
    if (e >= n_edges) return;

    int src, dst;
    if (d_is64) {
        const long long* p = (const long long*)ei;
        src = (int)p[e];
        dst = (int)p[n_edges + e];
    } else {
        const int* p = (const int*)ei;
        src = p[e];
        dst = p[n_edges + e];
    }

    int pos = atomicAdd(&d_deg[dst], 1);
    if (pos < CAP) {
        d_bucket[dst * CAP + pos] = src;
    } else {
        const float4* xs = (const float4*)(x + (size_t)src * CH);
        float* sp = d_s + (size_t)dst * CH;
        #pragma unroll 4
        for (int j = 0; j < CH / 4; j++) {
            float4 v = xs[j];
            asm volatile("red.global.add.v4.f32 [%0], {%1, %2, %3, %4};"
                         :: "l"(sp + j * 4), "f"(v.x), "f"(v.y), "f"(v.z), "f"(v.w)
                         : "memory");
        }
    }
}

// ---------------------------------------------------------------------------
// Gather: warp per node. acc = x[i] + overflow_residue + sum of bucketed
// neighbor rows; one write per row. Each lane owns one float4 of the row.
// ---------------------------------------------------------------------------
__global__ void gather_kernel(const float* __restrict__ x, int n_nodes) {
    int node = (blockIdx.x * blockDim.x + threadIdx.x) >> 5;
    int lane = threadIdx.x & 31;
    if (node >= n_nodes) return;

    int deg = d_deg[node];
    int nb  = min(deg, CAP);

    const size_t rb = (size_t)node * CH + lane * 4;
    float4 acc = *(const float4*)(x + rb);          // self loop
    float4 r   = *(const float4*)(d_s + rb);        // overflow residue (normally 0)
    acc.x += r.x; acc.y += r.y; acc.z += r.z; acc.w += r.w;

    int base = node * CAP;
    for (int e0 = 0; e0 < nb; e0 += 32) {
        int idx = 0;
        if (e0 + lane < nb) idx = d_bucket[base + e0 + lane];
        int m = min(32, nb - e0);
        for (int t = 0; t < m; t++) {
            int src = __shfl_sync(0xFFFFFFFFu, idx, t);
            float4 v = *(const float4*)(x + (size_t)src * CH + lane * 4);
            acc.x += v.x; acc.y += v.y; acc.z += v.z; acc.w += v.w;
        }
    }
    *(float4*)(d_s + rb) = acc;
}

// ---------------------------------------------------------------------------
// GEMM + epilogue: out = relu( (s @ W) / (deg+1) + bias )
// BM=128, BN=128, BK=16, 256 threads, 8x8 microtile split 2x(4) x 2x(4).
// Per kk-step: 4 x LDS.128 + 64 FFMA.
// ---------------------------------------------------------------------------
__global__ __launch_bounds__(256, 2)
void gemm_kernel(const float* __restrict__ W,
                 const float* __restrict__ bias,
                 float* __restrict__ out,
                 int n_nodes) {
    __shared__ float As[16][132];   // [k][m], pad 4 keeps 16B alignment per row
    __shared__ float Bs[16][128];   // [k][n]

    int tid = threadIdx.x;
    int tx  = tid & 15;    // col group
    int ty  = tid >> 4;    // row group
    int row0 = blockIdx.x * 128;

    float acc[2][4][2][4];   // [ri][i][ci][j]
    #pragma unroll
    for (int ri = 0; ri < 2; ri++)
        #pragma unroll
        for (int i = 0; i < 4; i++)
            #pragma unroll
            for (int ci = 0; ci < 2; ci++)
                #pragma unroll
                for (int j = 0; j < 4; j++)
                    acc[ri][i][ci][j] = 0.0f;

    for (int k0 = 0; k0 < CH; k0 += 16) {
        // A tile: As[k][m] = s[(row0+m)*CH + k0+k], float4 along k, transposed store
        #pragma unroll
        for (int i = 0; i < 2; i++) {
            int f   = tid + i * 256;      // 0..511
            int m   = f >> 2;
            int kq  = f & 3;
            int rg  = row0 + m;
            float4 v = make_float4(0.f, 0.f, 0.f, 0.f);
            if (rg < n_nodes)
                v = *(const float4*)(d_s + (size_t)rg * CH + k0 + kq * 4);
            As[kq * 4 + 0][m] = v.x;
            As[kq * 4 + 1][m] = v.y;
            As[kq * 4 + 2][m] = v.z;
            As[kq * 4 + 3][m] = v.w;
        }
        // B tile: Bs[k][n] = W[(k0+k)*CH + n]
        #pragma unroll
        for (int i = 0; i < 2; i++) {
            int f  = tid + i * 256;       // 0..511
            int k  = f >> 5;
            int n4 = f & 31;
            *(float4*)&Bs[k][n4 * 4] =
                *(const float4*)(W + (size_t)(k0 + k) * CH + n4 * 4);
        }
        __syncthreads();

        #pragma unroll
        for (int kk = 0; kk < 16; kk++) {
            float4 a0 = *(const float4*)&As[kk][ty * 4];
            float4 a1 = *(const float4*)&As[kk][64 + ty * 4];
            float4 b0 = *(const float4*)&Bs[kk][tx * 4];
            float4 b1 = *(const float4*)&Bs[kk][64 + tx * 4];
            float a[2][4] = {{a0.x, a0.y, a0.z, a0.w}, {a1.x, a1.y, a1.z, a1.w}};
            float b[2][4] = {{b0.x, b0.y, b0.z, b0.w}, {b1.x, b1.y, b1.z, b1.w}};
            #pragma unroll
            for (int ri = 0; ri < 2; ri++)
                #pragma unroll
                for (int i = 0; i < 4; i++)
                    #pragma unroll
                    for (int ci = 0; ci < 2; ci++)
                        #pragma unroll
                        for (int j = 0; j < 4; j++)
                            acc[ri][i][ci][j] = fmaf(a[ri][i], b[ci][j], acc[ri][i][ci][j]);
        }
        __syncthreads();
    }

    // Epilogue: /(deg+1), +bias, relu
    float4 bb0 = *(const float4*)(bias + tx * 4);
    float4 bb1 = *(const float4*)(bias + 64 + tx * 4);
    float bb[2][4] = {{bb0.x, bb0.y, bb0.z, bb0.w}, {bb1.x, bb1.y, bb1.z, bb1.w}};

    #pragma unroll
    for (int ri = 0; ri < 2; ri++) {
        #pragma unroll
        for (int i = 0; i < 4; i++) {
            int r = row0 + ri * 64 + ty * 4 + i;
            if (r < n_nodes) {
                float inv = 1.0f / (float)(d_deg[r] + 1);
                #pragma unroll
                for (int ci = 0; ci < 2; ci++) {
                    float4 o;
                    o.x = fmaxf(fmaf(acc[ri][i][ci][0], inv, bb[ci][0]), 0.0f);
                    o.y = fmaxf(fmaf(acc[ri][i][ci][1], inv, bb[ci][1]), 0.0f);
                    o.z = fmaxf(fmaf(acc[ri][i][ci][2], inv, bb[ci][2]), 0.0f);
                    o.w = fmaxf(fmaf(acc[ri][i][ci][3], inv, bb[ci][3]), 0.0f);
                    *(float4*)(out + (size_t)r * CH + ci * 64 + tx * 4) = o;
                }
            }
        }
    }
}

// ---------------------------------------------------------------------------
// kernel_launch
// Inputs: x[f32 N*128], edge_index[2*E], weight[f32 128*128],
//         u[f32 128], c[f32 1], bias[f32 128]
// u, c are dead: HEADS==1 => softmax over one element == 1.
// ---------------------------------------------------------------------------
extern "C" void kernel_launch(void* const* d_in, const int* in_sizes, int n_in,
                              void* d_out, int out_size) {
    const float* x    = (const float*)d_in[0];
    const void*  ei   = d_in[1];
    const float* W    = (const float*)d_in[2];
    const float* bias = (const float*)d_in[5];
    float* out = (float*)d_out;

    int n_nodes = in_sizes[0] / CH;
    int n_edges = in_sizes[1] / 2;

    detect_kernel<<<1, 1>>>(ei);

    int zthreads = n_nodes * (CH / 4);
    zero_kernel<<<(zthreads + 255) / 256, 256>>>(n_nodes);

    histo_fill_kernel<<<(n_edges + 255) / 256, 256>>>(x, ei, n_edges);

    int gwarps = n_nodes;                       // warp per node
    gather_kernel<<<(gwarps * 32 + 255) / 256, 256>>>(x, n_nodes);

    gemm_kernel<<<(n_nodes + 127) / 128, 256>>>(W, bias, out, n_nodes);
}